// round 5
// baseline (speedup 1.0000x reference)
#include <cuda_runtime.h>
#include <stdint.h>

// MeanAggregator: out[b, :] = mean over {neighbours[b,0..9], nodes[b]} of features[idx, :]
// B = 100000, K = 10, N = 1000000, D = 128 (fp32). Indices are int32 (JAX x64 disabled).
//
// D-split pass strategy: 4 passes over quarters of D (32 floats = 128 B per row per pass).
// Per-pass distinct-row footprint = ~667k lines x 128 B = 85 MB < L2 (126 MB), so all
// repeated row references hit L2 within a pass. gridDim.y = quarter (slowest-varying in
// block linearization) gives approximate quarter-major execution order.
//
// Warp per (row, quarter): lane l reads float (q*32 + l) of each of the 11 gathered rows
// -> 128 B fully coalesced per row reference.

#define B_NODES   100000
#define K_NEIGH   10
#define D_DIM     128
#define Q_DIM     32            // floats per quarter

__global__ __launch_bounds__(256, 4)
void mean_agg_kernel(const int*   __restrict__ nodes,
                     const int*   __restrict__ neighbours,
                     const float* __restrict__ features,
                     float*       __restrict__ out)
{
    const int warp = (blockIdx.x * blockDim.x + threadIdx.x) >> 5;
    const int lane = threadIdx.x & 31;
    const int q    = blockIdx.y;          // feature-dim quarter, slowest-varying
    if (warp >= B_NODES) return;

    // Gather the 11 row indices (converged loads, streaming policy).
    int idx[K_NEIGH + 1];
#pragma unroll
    for (int k = 0; k < K_NEIGH; ++k)
        idx[k] = __ldcs(&neighbours[warp * K_NEIGH + k]);
    idx[K_NEIGH] = __ldcs(&nodes[warp]);

    // This pass's column within each feature row.
    const float* fq = features + q * Q_DIM + lane;

    // Front-batch 11 independent 4B gathers (128 B/row across the warp) for max MLP.
    float v[K_NEIGH + 1];
#pragma unroll
    for (int k = 0; k < K_NEIGH + 1; ++k)
        v[k] = __ldg(fq + (long long)idx[k] * D_DIM);

    float acc = 0.f;
#pragma unroll
    for (int k = 0; k < K_NEIGH + 1; ++k)
        acc += v[k];

    acc *= (1.0f / (float)(K_NEIGH + 1));

    __stcs(&out[(long long)warp * D_DIM + q * Q_DIM + lane], acc);
}

extern "C" void kernel_launch(void* const* d_in, const int* in_sizes, int n_in,
                              void* d_out, int out_size)
{
    const int*   nodes      = (const int*)d_in[0];
    const int*   neighbours = (const int*)d_in[1];
    const float* features   = (const float*)d_in[2];
    float*       out        = (float*)d_out;

    const int threads = 256;                                      // 8 warps / block
    dim3 grid((B_NODES * 32 + threads - 1) / threads, 4);         // 12500 x 4 quarters
    mean_agg_kernel<<<grid, threads>>>(nodes, neighbours, features, out);
}

// round 6
// speedup vs baseline: 1.3650x; 1.3650x over previous
#include <cuda_runtime.h>
#include <stdint.h>

// MeanAggregator: out[b, :] = mean over {neighbours[b,0..9], nodes[b]} of features[idx, :]
// B = 100000, K = 10, N = 1000000, D = 128 (fp32). Indices int32 (JAX x64 disabled).
//
// D-split (4 quarters of 32 floats) keeps per-pass distinct-row footprint at
// ~667k x 128 B = 85 MB < L2 (126 MB) -> repeats hit L2 (verified R5: 416 MB DRAM).
// To keep DRAM efficiency (R5 lost it with 32-bit loads), each warp handles FOUR
// (row, quarter) pairs: 4 subgroups of 8 lanes; lane covers the quarter as float4.
// All gathers are LDG.128, 11 front-batched per lane for max MLP.

#define B_NODES   100000
#define K_NEIGH   10
#define D_DIM     128
#define Q_FLOATS  32
#define D_VEC     (D_DIM / 4)    // 32 float4 per row
#define Q_VEC     (Q_FLOATS / 4) // 8 float4 per quarter

__global__ __launch_bounds__(256, 2)
void mean_agg_kernel(const int*    __restrict__ nodes,
                     const int*    __restrict__ neighbours,
                     const float4* __restrict__ features,
                     float4*       __restrict__ out)
{
    const int warp = (blockIdx.x * blockDim.x + threadIdx.x) >> 5;  // 0..24999 per quarter
    const int lane = threadIdx.x & 31;
    const int sub  = lane >> 3;        // subgroup 0..3 -> row offset
    const int sl   = lane & 7;         // float4 slot within quarter
    const int q    = blockIdx.y;       // feature-dim quarter (slowest-varying)

    const int row = warp * 4 + sub;
    if (row >= B_NODES) return;

    // 11 row indices for this subgroup's row (converged within subgroup).
    int idx[K_NEIGH + 1];
#pragma unroll
    for (int k = 0; k < K_NEIGH; ++k)
        idx[k] = __ldcs(&neighbours[row * K_NEIGH + k]);
    idx[K_NEIGH] = __ldcs(&nodes[row]);

    // Base float4 pointer for this quarter+slot.
    const float4* fq = features + q * Q_VEC + sl;

    // Front-batch 11 independent LDG.128 gathers for max MLP.
    float4 v[K_NEIGH + 1];
#pragma unroll
    for (int k = 0; k < K_NEIGH + 1; ++k)
        v[k] = __ldg(fq + (long long)idx[k] * D_VEC);

    float4 acc = make_float4(0.f, 0.f, 0.f, 0.f);
#pragma unroll
    for (int k = 0; k < K_NEIGH + 1; ++k) {
        acc.x += v[k].x;
        acc.y += v[k].y;
        acc.z += v[k].z;
        acc.w += v[k].w;
    }

    const float s = 1.0f / (float)(K_NEIGH + 1);
    acc.x *= s; acc.y *= s; acc.z *= s; acc.w *= s;

    __stcs(&out[(long long)row * D_VEC + q * Q_VEC + sl], acc);
}

extern "C" void kernel_launch(void* const* d_in, const int* in_sizes, int n_in,
                              void* d_out, int out_size)
{
    const int*    nodes      = (const int*)d_in[0];
    const int*    neighbours = (const int*)d_in[1];
    const float4* features   = (const float4*)d_in[2];
    float4*       out        = (float4*)d_out;

    // One warp per 4 rows, per quarter: 25000 warps -> 3125 blocks of 256, x4 quarters.
    const int threads = 256;
    const int warps_needed = (B_NODES + 3) / 4;                       // 25000
    dim3 grid((warps_needed * 32 + threads - 1) / threads, 4);        // 3125 x 4
    mean_agg_kernel<<<grid, threads>>>(nodes, neighbours, features, out);
}